// round 11
// baseline (speedup 1.0000x reference)
#include <cuda_runtime.h>
#include <cuda_bf16.h>
#include <math_constants.h>
#include <cstdint>

#define HW 13
#define NTOK 169
#define BNP 192          // bf16 B-operand column stride
#define BATCH 256

typedef __nv_bfloat16 bf;

// ---- B-operand planes: [k][BNP] bf16, separate hi / lo ----
__device__ __align__(16) bf g_xh [BATCH * 512 * BNP], g_xl [BATCH * 512 * BNP];
__device__ __align__(16) bf g_f8h[BATCH * 256 * BNP], g_f8l[BATCH * 256 * BNP];
__device__ __align__(16) bf g_ph [BATCH * 128 * BNP], g_pl [BATCH * 128 * BNP];
__device__ __align__(16) bf g_Gh [BATCH * 64 * BNP],  g_Gl [BATCH * 64 * BNP];
__device__ __align__(16) bf g_Sh [BATCH * 192 * BNP], g_Sl [BATCH * 192 * BNP]; // rows 169+ stay 0
// ---- A-operand planes: [m][K] bf16 (row-major, K-contiguous) ----
__device__ __align__(16) bf g_fwh[64 * 512],  g_fwl[64 * 512];
__device__ __align__(16) bf g_gwh[64 * 512],  g_gwl[64 * 512];
__device__ __align__(16) bf g_hwh[192 * 256], g_hwl[192 * 256];
__device__ __align__(16) bf g_uwh[192 * 128], g_uwl[192 * 128];
__device__ __align__(16) bf g_cwh[512 * 192], g_cwl[512 * 192]; // cols 176+ stay 0
__device__ __align__(16) bf g_Fh [BATCH * 192 * 64], g_Fl[BATCH * 192 * 64];

// ============================================================
// low-level helpers
// ============================================================
__device__ __forceinline__ unsigned smem_u32(const void* p) {
    return (unsigned)__cvta_generic_to_shared(p);
}
__device__ __forceinline__ void cpa16(void* dst, const void* src) {
    asm volatile("cp.async.cg.shared.global [%0], [%1], 16;"
                 :: "r"(smem_u32(dst)), "l"(src));
}
#define CP_COMMIT()  asm volatile("cp.async.commit_group;")
#define CP_WAIT1()   asm volatile("cp.async.wait_group 1;")
#define CP_WAIT0()   asm volatile("cp.async.wait_group 0;")

__device__ __forceinline__ void ldsm_x4(unsigned (&r)[4], unsigned a) {
    asm volatile("ldmatrix.sync.aligned.m8n8.x4.shared.b16 {%0,%1,%2,%3}, [%4];"
        : "=r"(r[0]), "=r"(r[1]), "=r"(r[2]), "=r"(r[3]) : "r"(a));
}
__device__ __forceinline__ void ldsm_x4t(unsigned (&r)[4], unsigned a) {
    asm volatile("ldmatrix.sync.aligned.m8n8.x4.trans.shared.b16 {%0,%1,%2,%3}, [%4];"
        : "=r"(r[0]), "=r"(r[1]), "=r"(r[2]), "=r"(r[3]) : "r"(a));
}
__device__ __forceinline__ void ldsm_x2t(unsigned (&r)[2], unsigned a) {
    asm volatile("ldmatrix.sync.aligned.m8n8.x2.trans.shared.b16 {%0,%1}, [%2];"
        : "=r"(r[0]), "=r"(r[1]) : "r"(a));
}
__device__ __forceinline__ void mma16816(float (&d)[4], const unsigned (&a)[4],
                                         unsigned b0, unsigned b1) {
    asm volatile("mma.sync.aligned.m16n8k16.row.col.f32.bf16.bf16.f32 "
        "{%0,%1,%2,%3}, {%4,%5,%6,%7}, {%8,%9}, {%0,%1,%2,%3};"
        : "+f"(d[0]), "+f"(d[1]), "+f"(d[2]), "+f"(d[3])
        : "r"(a[0]), "r"(a[1]), "r"(a[2]), "r"(a[3]), "r"(b0), "r"(b1));
}
__device__ __forceinline__ void split_bf(float v, bf& hi, bf& lo) {
    hi = __float2bfloat16(v);
    lo = __float2bfloat16(v - __bfloat162float(hi));
}

// ============================================================
// split-N GEMM machinery (fg / out): N covered 96 cols per CTA,
// warp grid 4M x 2N (n48 per warp), acc[6][4] = 24 regs -> 3 CTAs/SM
// ============================================================
struct SmemN {
    bf Ah[2][64][40];     // 10240 B
    bf Al[2][64][40];
    bf Bh[2][32][104];    // 13312 B
    bf Bl[2][32][104];
};                         // total 47104 B
#define SMEMN_BYTES sizeof(SmemN)

__device__ __forceinline__ void fill_n(SmemN& s, int buf,
                                       const bf* __restrict__ Ah, const bf* __restrict__ Al,
                                       int lda,
                                       const bf* __restrict__ Bh, const bf* __restrict__ Bl,
                                       int n0, int k0, int tid)
{
#pragma unroll
    for (int i = 0; i < 2; i++) {       // A: 512 x 16B units
        int idx = tid + i * 256;
        int var = idx >> 8;
        int j = idx & 255;
        int r = j >> 2, q = j & 3;
        const bf* src = (var ? Al : Ah) + (size_t)r * lda + k0 + q * 8;
        bf* dst = var ? &s.Al[buf][r][q * 8] : &s.Ah[buf][r][q * 8];
        cpa16(dst, src);
    }
#pragma unroll
    for (int i = 0; i < 3; i++) {       // B: 768 x 16B units (32 rows x 96 cols x 2 planes)
        int idx = tid + i * 256;
        int var = idx >= 384;
        int j = idx - (var ? 384 : 0);
        int rr = j / 12, q = j - rr * 12;
        const bf* src = (var ? Bl : Bh) + (size_t)(k0 + rr) * BNP + n0 + q * 8;
        bf* dst = var ? &s.Bl[buf][rr][q * 8] : &s.Bh[buf][rr][q * 8];
        cpa16(dst, src);
    }
}

__device__ __forceinline__ void mma_chunk_n(float (&acc)[6][4], SmemN& s, int buf,
                                            int lane, int wm, int wn)
{
    unsigned rsel = lane & 15;
    unsigned csel = (lane >> 4) << 3;
#pragma unroll
    for (int ks = 0; ks < 32; ks += 16) {
        unsigned ah[4], al[4];
        ldsm_x4(ah, smem_u32(&s.Ah[buf][wm * 16 + rsel][ks + csel]));
        ldsm_x4(al, smem_u32(&s.Al[buf][wm * 16 + rsel][ks + csel]));
#pragma unroll
        for (int g = 0; g < 3; g++) {
            unsigned bh[4], bl[4];
            ldsm_x4t(bh, smem_u32(&s.Bh[buf][ks + rsel][wn * 48 + g * 16 + csel]));
            ldsm_x4t(bl, smem_u32(&s.Bl[buf][ks + rsel][wn * 48 + g * 16 + csel]));
            mma16816(acc[2 * g],     ah, bh[0], bh[1]);
            mma16816(acc[2 * g],     ah, bl[0], bl[1]);
            mma16816(acc[2 * g],     al, bh[0], bh[1]);
            mma16816(acc[2 * g + 1], ah, bh[2], bh[3]);
            mma16816(acc[2 * g + 1], ah, bl[2], bl[3]);
            mma16816(acc[2 * g + 1], al, bh[2], bh[3]);
        }
    }
}

__device__ __forceinline__ void run_gemm_n(SmemN& s, float (&acc)[6][4],
                                           const bf* __restrict__ Ah, const bf* __restrict__ Al,
                                           int lda,
                                           const bf* __restrict__ Bh, const bf* __restrict__ Bl,
                                           int n0, int K, int tid, int lane, int wm, int wn)
{
    int nt = K >> 5;
    fill_n(s, 0, Ah, Al, lda, Bh, Bl, n0, 0, tid);
    CP_COMMIT();
    for (int t = 0; t < nt; t++) {
        if (t + 1 < nt) {
            fill_n(s, (t + 1) & 1, Ah, Al, lda, Bh, Bl, n0, (t + 1) * 32, tid);
            CP_COMMIT();
            CP_WAIT1();
        } else {
            CP_WAIT0();
        }
        __syncthreads();
        mma_chunk_n(acc, s, t & 1, lane, wm, wn);
        __syncthreads();
    }
}

// ============================================================
// full-N GEMM machinery (s_kernel; unchanged from R9)
// ============================================================
struct Smem {
    bf Ah[2][64][40];
    bf Al[2][64][40];
    bf Bh[2][32][184];
    bf Bl[2][32][184];
};
#define SMEM_BYTES sizeof(Smem)

__device__ __forceinline__ void fill(Smem& s, int buf,
                                     const bf* __restrict__ Ah, const bf* __restrict__ Al,
                                     int lda,
                                     const bf* __restrict__ Bh, const bf* __restrict__ Bl,
                                     int k0, int tid)
{
#pragma unroll
    for (int i = 0; i < 2; i++) {
        int idx = tid + i * 256;
        int var = idx >> 8;
        int j = idx & 255;
        int r = j >> 2, q = j & 3;
        const bf* src = (var ? Al : Ah) + (size_t)r * lda + k0 + q * 8;
        bf* dst = var ? &s.Al[buf][r][q * 8] : &s.Ah[buf][r][q * 8];
        cpa16(dst, src);
    }
#pragma unroll
    for (int i = 0; i < 6; i++) {
        int idx = tid + i * 256;
        if (idx < 1408) {
            int var = idx >= 704;
            int j = idx - (var ? 704 : 0);
            int rr = j / 22, q = j - rr * 22;
            const bf* src = (var ? Bl : Bh) + (size_t)(k0 + rr) * BNP + q * 8;
            bf* dst = var ? &s.Bl[buf][rr][q * 8] : &s.Bh[buf][rr][q * 8];
            cpa16(dst, src);
        }
    }
}

__device__ __forceinline__ void mma_chunk(float (&acc)[11][4], Smem& s, int buf,
                                          int lane, int wm, int wn)
{
    unsigned rsel = lane & 15;
    unsigned csel = (lane >> 4) << 3;
#pragma unroll
    for (int ks = 0; ks < 32; ks += 16) {
        unsigned ah[4], al[4];
        ldsm_x4(ah, smem_u32(&s.Ah[buf][wm * 16 + rsel][ks + csel]));
        ldsm_x4(al, smem_u32(&s.Al[buf][wm * 16 + rsel][ks + csel]));
#pragma unroll
        for (int g = 0; g < 5; g++) {
            unsigned bh[4], bl[4];
            ldsm_x4t(bh, smem_u32(&s.Bh[buf][ks + rsel][wn * 88 + g * 16 + csel]));
            ldsm_x4t(bl, smem_u32(&s.Bl[buf][ks + rsel][wn * 88 + g * 16 + csel]));
            mma16816(acc[2 * g],     ah, bh[0], bh[1]);
            mma16816(acc[2 * g],     ah, bl[0], bl[1]);
            mma16816(acc[2 * g],     al, bh[0], bh[1]);
            mma16816(acc[2 * g + 1], ah, bh[2], bh[3]);
            mma16816(acc[2 * g + 1], ah, bl[2], bl[3]);
            mma16816(acc[2 * g + 1], al, bh[2], bh[3]);
        }
        unsigned bh2[2], bl2[2];
        ldsm_x2t(bh2, smem_u32(&s.Bh[buf][ks + rsel][wn * 88 + 80]));
        ldsm_x2t(bl2, smem_u32(&s.Bl[buf][ks + rsel][wn * 88 + 80]));
        mma16816(acc[10], ah, bh2[0], bh2[1]);
        mma16816(acc[10], ah, bl2[0], bl2[1]);
        mma16816(acc[10], al, bh2[0], bh2[1]);
    }
}

__device__ __forceinline__ void run_gemm(Smem& s, float (&acc)[11][4],
                                         const bf* __restrict__ Ah, const bf* __restrict__ Al,
                                         int lda,
                                         const bf* __restrict__ Bh, const bf* __restrict__ Bl,
                                         int K, int tid, int lane, int wm, int wn)
{
    int nt = K >> 5;
    fill(s, 0, Ah, Al, lda, Bh, Bl, 0, tid);
    CP_COMMIT();
    for (int t = 0; t < nt; t++) {
        if (t + 1 < nt) {
            fill(s, (t + 1) & 1, Ah, Al, lda, Bh, Bl, (t + 1) * 32, tid);
            CP_COMMIT();
            CP_WAIT1();
        } else {
            CP_WAIT0();
        }
        __syncthreads();
        mma_chunk(acc, s, t & 1, lane, wm, wn);
        __syncthreads();
    }
}

// ============================================================
// split / repack kernels
// ============================================================
__global__ __launch_bounds__(256) void split_w_kernel(
    const float* __restrict__ f_w, const float* __restrict__ g_w,
    const float* __restrict__ h_w, const float* __restrict__ u_w,
    const float* __restrict__ c_w)
{
    int idx = blockIdx.x * 256 + threadIdx.x;
    float v; bf *dh, *dl;
    if (idx < 64 * 512) {
        v = f_w[idx]; dh = g_fwh + idx; dl = g_fwl + idx;
    } else if ((idx -= 64 * 512) < 64 * 512) {
        v = g_w[idx]; dh = g_gwh + idx; dl = g_gwl + idx;
    } else if ((idx -= 64 * 512) < 169 * 256) {
        v = h_w[idx]; dh = g_hwh + idx; dl = g_hwl + idx;
    } else if ((idx -= 169 * 256) < 169 * 128) {
        v = u_w[idx]; dh = g_uwh + idx; dl = g_uwl + idx;
    } else if ((idx -= 169 * 128) < 512 * 169) {
        int m = idx / 169, k = idx - m * 169;
        v = c_w[idx];
        dh = g_cwh + (size_t)m * 192 + k; dl = g_cwl + (size_t)m * 192 + k;
    } else return;
    bf hi, lo; split_bf(v, hi, lo);
    *dh = hi; *dl = lo;
}

#define XE (BATCH * 512 * NTOK)
#define FE (BATCH * 256 * NTOK)
__global__ __launch_bounds__(256) void split_x_kernel(const float* __restrict__ x,
                                                      const float* __restrict__ f8)
{
    int idx = blockIdx.x * 256 + threadIdx.x;
    const float* src; bf *bh, *bl;
    if (idx < XE)              { src = x;  bh = g_xh;  bl = g_xl; }
    else if ((idx -= XE) < FE) { src = f8; bh = g_f8h; bl = g_f8l; }
    else return;
    int row = idx / NTOK, n = idx - row * NTOK;
    bf hi, lo; split_bf(src[idx], hi, lo);
    size_t o = (size_t)row * BNP + n;
    bh[o] = hi; bl[o] = lo;
}

// ============================================================
// antialiased bilinear 26 -> 13 (jax antialias=True), writes split bf16
// ============================================================
__constant__ int   c_tap0[HW] = { 0, 1, 3, 5, 7, 9,11,13,15,17,19,21,23};
__constant__ float c_wt[HW][4] = {
    {3.f/7.f, 3.f/7.f, 1.f/7.f, 0.f},
    {0.125f, 0.375f, 0.375f, 0.125f}, {0.125f, 0.375f, 0.375f, 0.125f},
    {0.125f, 0.375f, 0.375f, 0.125f}, {0.125f, 0.375f, 0.375f, 0.125f},
    {0.125f, 0.375f, 0.375f, 0.125f}, {0.125f, 0.375f, 0.375f, 0.125f},
    {0.125f, 0.375f, 0.375f, 0.125f}, {0.125f, 0.375f, 0.375f, 0.125f},
    {0.125f, 0.375f, 0.375f, 0.125f}, {0.125f, 0.375f, 0.375f, 0.125f},
    {0.125f, 0.375f, 0.375f, 0.125f},
    {1.f/7.f, 3.f/7.f, 3.f/7.f, 0.f}
};

__global__ __launch_bounds__(256) void pool_kernel(const float* __restrict__ f5) {
    int idx = blockIdx.x * blockDim.x + threadIdx.x;
    if (idx >= BATCH * 128 * NTOK) return;
    int n  = idx % NTOK;
    int bc = idx / NTOK;
    int j = n % HW, i = n / HW;
    const float* src = f5 + (size_t)bc * 26 * 26;
    int r0 = c_tap0[i], cc0 = c_tap0[j];
    float acc = 0.f;
#pragma unroll
    for (int ri = 0; ri < 4; ri++) {
        float wr = c_wt[i][ri];
        if (wr == 0.f) continue;
        int r = r0 + ri;
        float rowv = 0.f;
#pragma unroll
        for (int ci = 0; ci < 4; ci++) {
            float wc = c_wt[j][ci];
            if (wc == 0.f) continue;
            rowv = fmaf(wc, src[r * 26 + cc0 + ci], rowv);
        }
        acc = fmaf(wr, rowv, acc);
    }
    bf hi, lo; split_bf(acc, hi, lo);
    size_t o = (size_t)bc * BNP + n;
    g_ph[o] = hi; g_pl[o] = lo;
}

// ============================================================
// F / G projections: grid (4, BATCH) — x = isG, y = nsel
// ============================================================
__global__ __launch_bounds__(256, 3) void fg_kernel(const float* __restrict__ f_b,
                                                    const float* __restrict__ g_b)
{
    extern __shared__ char smem_raw[];
    SmemN& s = *reinterpret_cast<SmemN*>(smem_raw);
    int b    = blockIdx.y;
    bool isG = (blockIdx.x & 1) != 0;
    int n0   = (blockIdx.x >> 1) * 96;
    int tid = threadIdx.x, lane = tid & 31, wid = tid >> 5;
    int wm = wid & 3, wn = wid >> 2;

    float acc[6][4] = {};
    run_gemm_n(s, acc, isG ? g_gwh : g_fwh, isG ? g_gwl : g_fwl, 512,
               g_xh + (size_t)b * 512 * BNP, g_xl + (size_t)b * 512 * BNP,
               n0, 512, tid, lane, wm, wn);

    const float* bias = isG ? g_b : f_b;
    int lr = lane >> 2, lc = (lane & 3) * 2;
#pragma unroll
    for (int half = 0; half < 2; half++) {
        int m = wm * 16 + lr + half * 8;
        float bv = bias[m];
#pragma unroll
        for (int t = 0; t < 6; t++) {
#pragma unroll
            for (int e = 0; e < 2; e++) {
                int n = n0 + wn * 48 + t * 8 + lc + e;
                if (n >= NTOK) continue;
                float v = acc[t][half * 2 + e] + bv;
                bf hi, lo; split_bf(v, hi, lo);
                if (isG) {
                    size_t o = (size_t)(b * 64 + m) * BNP + n;
                    g_Gh[o] = hi; g_Gl[o] = lo;
                } else {
                    size_t o = (size_t)(b * 192 + n) * 64 + m;
                    g_Fh[o] = hi; g_Fl[o] = lo;
                }
            }
        }
    }
}

// ============================================================
// S = softmax(F^T G) + h_w@f8 + u_w@pool + bias     grid (3, BATCH)
// ============================================================
__global__ __launch_bounds__(256, 2) void s_kernel(const float* __restrict__ h_b,
                                                   const float* __restrict__ u_b)
{
    extern __shared__ char smem_raw[];
    Smem& s = *reinterpret_cast<Smem*>(smem_raw);
    __shared__ float redM[2][64], redS[2][64];
    int b   = blockIdx.y;
    int m0  = blockIdx.x * 64;
    int tid = threadIdx.x, lane = tid & 31, wid = tid >> 5;
    int wm = wid & 3, wn = wid >> 2;
    int lr = lane >> 2, lc = (lane & 3) * 2;

    float acc[11][4] = {};

    run_gemm(s, acc, g_Fh + (size_t)(b * 192 + m0) * 64,
                     g_Fl + (size_t)(b * 192 + m0) * 64, 64,
             g_Gh + (size_t)b * 64 * BNP, g_Gl + (size_t)b * 64 * BNP, 64,
             tid, lane, wm, wn);

    float pmax[2] = { -CUDART_INF_F, -CUDART_INF_F };
#pragma unroll
    for (int half = 0; half < 2; half++)
#pragma unroll
        for (int t = 0; t < 11; t++)
#pragma unroll
            for (int e = 0; e < 2; e++) {
                int n = wn * 88 + t * 8 + lc + e;
                if (n < NTOK) pmax[half] = fmaxf(pmax[half], acc[t][half * 2 + e]);
            }
#pragma unroll
    for (int off = 1; off < 4; off <<= 1) {
        pmax[0] = fmaxf(pmax[0], __shfl_xor_sync(0xffffffffu, pmax[0], off, 4));
        pmax[1] = fmaxf(pmax[1], __shfl_xor_sync(0xffffffffu, pmax[1], off, 4));
    }
    if ((lane & 3) == 0) {
        redM[wn][wm * 16 + lr]     = pmax[0];
        redM[wn][wm * 16 + 8 + lr] = pmax[1];
    }
    __syncthreads();
    float mx[2] = { fmaxf(redM[0][wm * 16 + lr],     redM[1][wm * 16 + lr]),
                    fmaxf(redM[0][wm * 16 + 8 + lr], redM[1][wm * 16 + 8 + lr]) };
    float psum[2] = { 0.f, 0.f };
#pragma unroll
    for (int half = 0; half < 2; half++)
#pragma unroll
        for (int t = 0; t < 11; t++)
#pragma unroll
            for (int e = 0; e < 2; e++) {
                int n = wn * 88 + t * 8 + lc + e;
                float ev = (n < NTOK) ? __expf(acc[t][half * 2 + e] - mx[half]) : 0.f;
                acc[t][half * 2 + e] = ev;
                psum[half] += ev;
            }
#pragma unroll
    for (int off = 1; off < 4; off <<= 1) {
        psum[0] += __shfl_xor_sync(0xffffffffu, psum[0], off, 4);
        psum[1] += __shfl_xor_sync(0xffffffffu, psum[1], off, 4);
    }
    if ((lane & 3) == 0) {
        redS[wn][wm * 16 + lr]     = psum[0];
        redS[wn][wm * 16 + 8 + lr] = psum[1];
    }
    __syncthreads();
    float inv[2] = { 1.f / (redS[0][wm * 16 + lr]     + redS[1][wm * 16 + lr]),
                     1.f / (redS[0][wm * 16 + 8 + lr] + redS[1][wm * 16 + 8 + lr]) };
#pragma unroll
    for (int half = 0; half < 2; half++)
#pragma unroll
        for (int t = 0; t < 11; t++)
#pragma unroll
            for (int e = 0; e < 2; e++)
                acc[t][half * 2 + e] *= inv[half];
    __syncthreads();

    run_gemm(s, acc, g_hwh + (size_t)m0 * 256, g_hwl + (size_t)m0 * 256, 256,
             g_f8h + (size_t)b * 256 * BNP, g_f8l + (size_t)b * 256 * BNP, 256,
             tid, lane, wm, wn);
    run_gemm(s, acc, g_uwh + (size_t)m0 * 128, g_uwl + (size_t)m0 * 128, 128,
             g_ph + (size_t)b * 128 * BNP, g_pl + (size_t)b * 128 * BNP, 128,
             tid, lane, wm, wn);

#pragma unroll
    for (int half = 0; half < 2; half++) {
        int row = m0 + wm * 16 + lr + half * 8;
        if (row >= NTOK) continue;
        float bv = h_b[row] + u_b[row];
        size_t ro = (size_t)(b * 192 + row) * BNP;
#pragma unroll
        for (int t = 0; t < 11; t++)
#pragma unroll
            for (int e = 0; e < 2; e++) {
                int n = wn * 88 + t * 8 + lc + e;
                if (n < NTOK) {
                    bf hi, lo; split_bf(acc[t][half * 2 + e] + bv, hi, lo);
                    g_Sh[ro + n] = hi; g_Sl[ro + n] = lo;
                }
            }
    }
}

// ============================================================
// out = gamma * (c_w @ S + c_b) + x     grid (16, BATCH), K = 192
// blockIdx.x: bit0 = nsel, bits1+ = mtile
// ============================================================
__global__ __launch_bounds__(256, 3) void out_kernel(const float* __restrict__ c_b,
                                                     const float* __restrict__ x,
                                                     const float* __restrict__ gamma_p,
                                                     float* __restrict__ Out)
{
    extern __shared__ char smem_raw[];
    SmemN& s = *reinterpret_cast<SmemN*>(smem_raw);
    int b   = blockIdx.y;
    int m0  = (blockIdx.x >> 1) * 64;
    int n0  = (blockIdx.x & 1) * 96;
    int tid = threadIdx.x, lane = tid & 31, wid = tid >> 5;
    int wm = wid & 3, wn = wid >> 2;
    int lr = lane >> 2, lc = (lane & 3) * 2;

    float acc[6][4] = {};
    run_gemm_n(s, acc, g_cwh + (size_t)m0 * 192, g_cwl + (size_t)m0 * 192, 192,
               g_Sh + (size_t)b * 192 * BNP, g_Sl + (size_t)b * 192 * BNP,
               n0, 192, tid, lane, wm, wn);

    float gma = *gamma_p;
#pragma unroll
    for (int half = 0; half < 2; half++) {
        int m = m0 + wm * 16 + lr + half * 8;
        float bv = c_b[m];
        const float* xrow = x + (size_t)b * 512 * NTOK + (size_t)m * NTOK;
        float* orow = Out + (size_t)b * 512 * NTOK + (size_t)m * NTOK;
#pragma unroll
        for (int t = 0; t < 6; t++)
#pragma unroll
            for (int e = 0; e < 2; e++) {
                int n = n0 + wn * 48 + t * 8 + lc + e;
                if (n < NTOK)
                    orow[n] = fmaf(gma, acc[t][half * 2 + e] + bv, xrow[n]);
            }
    }
}

// ============================================================
extern "C" void kernel_launch(void* const* d_in, const int* in_sizes, int n_in,
                              void* d_out, int out_size)
{
    const float* x    = (const float*)d_in[0];
    const float* f5   = (const float*)d_in[1];
    const float* f8   = (const float*)d_in[2];
    const float* f_w  = (const float*)d_in[3];
    const float* f_b  = (const float*)d_in[4];
    const float* g_w  = (const float*)d_in[5];
    const float* g_b  = (const float*)d_in[6];
    const float* h_w  = (const float*)d_in[7];
    const float* h_b  = (const float*)d_in[8];
    const float* u_w  = (const float*)d_in[9];
    const float* u_b  = (const float*)d_in[10];
    const float* c_w  = (const float*)d_in[11];
    const float* c_b  = (const float*)d_in[12];
    const float* gma  = (const float*)d_in[13];

    float* out = (float*)d_out;

    cudaFuncSetAttribute(fg_kernel,  cudaFuncAttributeMaxDynamicSharedMemorySize, (int)SMEMN_BYTES);
    cudaFuncSetAttribute(s_kernel,   cudaFuncAttributeMaxDynamicSharedMemorySize, (int)SMEM_BYTES);
    cudaFuncSetAttribute(out_kernel, cudaFuncAttributeMaxDynamicSharedMemorySize, (int)SMEMN_BYTES);

    int wtot = 2 * 64 * 512 + 169 * 256 + 169 * 128 + 512 * 169;
    split_w_kernel<<<(wtot + 255) / 256, 256>>>(f_w, g_w, h_w, u_w, c_w);
    split_x_kernel<<<(XE + FE + 255) / 256, 256>>>(x, f8);
    {
        int total = BATCH * 128 * NTOK;
        pool_kernel<<<(total + 255) / 256, 256>>>(f5);
    }
    fg_kernel<<<dim3(4, BATCH), 256, SMEMN_BYTES>>>(f_b, g_b);
    s_kernel<<<dim3(3, BATCH), 256, SMEM_BYTES>>>(h_b, u_b);
    out_kernel<<<dim3(16, BATCH), 256, SMEMN_BYTES>>>(c_b, x, gma, out);
}